// round 7
// baseline (speedup 1.0000x reference)
#include <cuda_runtime.h>
#include <cstdint>
#include <cstddef>
#include <math.h>

#define NBLK 128
#define NTHR 512

// ------------------------- device scratch (static, no allocs) -------------------------
__device__ float    g_EW[4096u * 1024u];        // [row][c]: E@W_ih1[:, :256]^T + b_ih1 + b_hh1
__device__ float    g_Gpre[256u * 1024u * 64u]; // [t][c][b]: embedding gate bias per step
__device__ float    g_AllT[256u * 256u * 64u];  // [t][c][b], c<128 h2, c>=128 ctx
__device__ float    g_ET[256u * 4096u];         // E transposed: [c][v]
// packed k-major state: idx(k,b) = (k>>2)*256 + b*4 + (k&3)
__device__ float    g_ctx[32 * 256];            // ctx (128 k)
__device__ float    g_h1[64 * 256];             // h1 (256 k)
__device__ float    g_h2[32 * 256];             // h2 (128 k)
__device__ float    g_P1b[1024 * 64];           // [c][b]: h1@W_hh1 partial for next step
__device__ float    g_P2b[512 * 64];            // [c2][b]: h2@W_hh2 partial for next step
__device__ float    g_c1[256 * 64];
__device__ float    g_c2[128 * 64];
__device__ unsigned g_slots[NBLK];

__device__ __forceinline__ float sigm(float x) { return 1.0f / (1.0f + __expf(-x)); }
__device__ __forceinline__ float ftanh(float x) {
    float cx = fminf(fmaxf(x, -15.f), 15.f);
    float e = __expf(2.f * cx);
    return (e - 1.f) / (e + 1.f);
}

// Atomic-free grid barrier: block i release-stores epoch to slot i; all blocks
// poll the slot vector until min >= epoch.
__device__ __forceinline__ void gbar(unsigned epoch) {
    __syncthreads();
    if (threadIdx.x == 0) {
        __threadfence();
        asm volatile("st.release.gpu.u32 [%0], %1;"
                     :: "l"(&g_slots[blockIdx.x]), "r"(epoch) : "memory");
    }
    bool ok;
    do {
        unsigned v = epoch;
        if (threadIdx.x < NBLK)
            asm volatile("ld.acquire.gpu.u32 %0, [%1];"
                         : "=r"(v) : "l"(&g_slots[threadIdx.x]) : "memory");
        ok = (v >= epoch);
    } while (!__syncthreads_and((int)ok));
}

// ------------------------- kernel 0: zero state -------------------------
__global__ void prep_k() {
    int i0 = blockIdx.x * blockDim.x + threadIdx.x;
    int st = gridDim.x * blockDim.x;
    for (int i = i0; i < 32 * 256; i += st) g_ctx[i] = 0.f;
    for (int i = i0; i < 256 * 64; i += st) g_c1[i] = 0.f;
    for (int i = i0; i < 128 * 64; i += st) g_c2[i] = 0.f;
    for (int i = i0; i < 1024 * 64; i += st) g_P1b[i] = 0.f;
    for (int i = i0; i < 512 * 64; i += st) g_P2b[i] = 0.f;
    if (i0 < NBLK) g_slots[i0] = 0u;
}

// ------------------------- kernel 1: EW[v][c] = E[v,:] . W_ih1[c, :256] + bias -------------------------
__global__ void __launch_bounds__(256) ew_k(const float* __restrict__ E,
                                            const float* __restrict__ W_ih1,
                                            const float* __restrict__ b_ih1,
                                            const float* __restrict__ b_hh1) {
    __shared__ __align__(16) float sA[16][68];
    __shared__ __align__(16) float sB[16][68];
    const int c0 = blockIdx.x * 64, v0 = blockIdx.y * 64;
    const int tid = threadIdx.x;
    const int lw = tid >> 2, kq = tid & 3;
    const int cx = tid & 15, vxx = tid >> 4;
    float4 acc[4];
    acc[0] = acc[1] = acc[2] = acc[3] = make_float4(0, 0, 0, 0);
    for (int k0 = 0; k0 < 256; k0 += 16) {
        float4 av = *(const float4*)(E + (size_t)(v0 + lw) * 256 + k0 + kq * 4);
        float4 bv = *(const float4*)(W_ih1 + (size_t)(c0 + lw) * 384 + k0 + kq * 4);
        __syncthreads();
        sA[kq * 4 + 0][lw] = av.x; sA[kq * 4 + 1][lw] = av.y;
        sA[kq * 4 + 2][lw] = av.z; sA[kq * 4 + 3][lw] = av.w;
        sB[kq * 4 + 0][lw] = bv.x; sB[kq * 4 + 1][lw] = bv.y;
        sB[kq * 4 + 2][lw] = bv.z; sB[kq * 4 + 3][lw] = bv.w;
        __syncthreads();
#pragma unroll
        for (int k = 0; k < 16; k++) {
            float4 cv = *(const float4*)&sB[k][cx * 4];
            float4 vv = *(const float4*)&sA[k][vxx * 4];
            float vs[4] = {vv.x, vv.y, vv.z, vv.w};
#pragma unroll
            for (int vi = 0; vi < 4; vi++) {
                acc[vi].x = fmaf(vs[vi], cv.x, acc[vi].x);
                acc[vi].y = fmaf(vs[vi], cv.y, acc[vi].y);
                acc[vi].z = fmaf(vs[vi], cv.z, acc[vi].z);
                acc[vi].w = fmaf(vs[vi], cv.w, acc[vi].w);
            }
        }
    }
    float4 bi = *(const float4*)(b_ih1 + c0 + cx * 4);
    float4 bh = *(const float4*)(b_hh1 + c0 + cx * 4);
    float4 bias = make_float4(bi.x + bh.x, bi.y + bh.y, bi.z + bh.z, bi.w + bh.w);
#pragma unroll
    for (int vi = 0; vi < 4; vi++) {
        float4 r = make_float4(acc[vi].x + bias.x, acc[vi].y + bias.y,
                               acc[vi].z + bias.z, acc[vi].w + bias.w);
        *(float4*)(g_EW + (size_t)(v0 + vxx * 4 + vi) * 1024 + c0 + cx * 4) = r;
    }
}

// ------------------------- kernel 1b: Gpre[t][c][b] = EW[text[b][t]][c] -------------------------
__global__ void __launch_bounds__(512) gpre_k(const int* __restrict__ text) {
    const int t = blockIdx.x;
    const int tid = threadIdx.x;
    const int b = tid & 63, cs = tid >> 6;
    const int row = text[b * 256 + t] & 4095;
    const float* src = g_EW + (size_t)row * 1024;
    float* dst = g_Gpre + (size_t)t * 65536;
    for (int c = cs; c < 1024; c += 8)
        dst[c * 64 + b] = src[c];
}

// ------------------------- kernel 1c: ET[c][v] = E[v][c] -------------------------
__global__ void __launch_bounds__(256) et_k(const float* __restrict__ E) {
    __shared__ float sT[32][33];
    const int v0 = blockIdx.x * 32, c0 = blockIdx.y * 32;
    const int tx = threadIdx.x & 31, ty = threadIdx.x >> 5;
#pragma unroll
    for (int i = 0; i < 4; i++)
        sT[ty + i * 8][tx] = E[(size_t)(v0 + ty + i * 8) * 256 + c0 + tx];
    __syncthreads();
#pragma unroll
    for (int i = 0; i < 4; i++)
        g_ET[(size_t)(c0 + ty + i * 8) * 4096 + v0 + tx] = sT[tx][ty + i * 8];
}

// ------------------------- kernel 2: persistent recurrence -------------------------
// Phase A (all blocks):  gates1 = ctx@W1a + g_P1b + Gpre -> cell -> h1
// Phase B (all blocks):  gates2 = h1@W2a + g_P2b + bias  -> cell -> h2
// Phase C: blocks 0-63 attention (h2,key,values -> ctx); blocks 64-127 compute
//          g_P1b = h1@W_hh1 and g_P2b = h2@W_hh2 for the NEXT step.
__global__ void __launch_bounds__(NTHR, 1) recur_k(
    const float* __restrict__ key, const float* __restrict__ values,
    const float* __restrict__ W_ih1, const float* __restrict__ W_hh1,
    const float* __restrict__ W_ih2, const float* __restrict__ W_hh2,
    const float* __restrict__ b_ih2, const float* __restrict__ b_hh2) {
    __shared__ __align__(16) float sW1a[128 * 8];   // [k][a] ctx weights
    __shared__ __align__(16) float sW2a[256 * 4];   // [k][q] h1->lstm2 weights
    __shared__ __align__(16) float sW1b[256 * 16];  // [k][j] W_hh1 slice (blocks>=64)
    __shared__ __align__(16) float sW2b[128 * 8];   // [k][j] W_hh2 slice (blocks>=64)
    __shared__ __align__(16) float sP[4096];        // partials / attention scratch
    __shared__ float sG[8 * 64];
    __shared__ float sB2[4];

    float* sEn  = sP;          // [512]
    float* sVal = sP + 512;    // [16*128]
    float* sH2f = sP + 2560;   // [128]
    float* sRed = sP + 2688;   // [32]

    const int tid = threadIdx.x;
    const int bid = blockIdx.x;
    const int b = tid & 63, ks = tid >> 6;   // 8 k-splits x 64 batch
    const int lane = tid & 31, wrp = tid >> 5;

    // ---- weight staging ----
    for (int i = tid; i < 128 * 8; i += NTHR) {
        int k = i >> 3, a = i & 7;
        int c = (a >> 1) * 256 + bid * 2 + (a & 1);
        sW1a[i] = W_ih1[(size_t)c * 384 + 256 + k];
    }
    for (int i = tid; i < 256 * 4; i += NTHR) {
        int k = i >> 2, q = i & 3;
        int c2 = q * 128 + bid;
        sW2a[i] = W_ih2[(size_t)c2 * 256 + k];
    }
    if (bid >= 64) {
        const int r = bid - 64;
        for (int i = tid; i < 256 * 16; i += NTHR) {
            int k = i >> 4, j = i & 15;
            sW1b[i] = W_hh1[(size_t)(r * 16 + j) * 256 + k];
        }
        for (int i = tid; i < 128 * 8; i += NTHR) {
            int k = i >> 3, j = i & 7;
            sW2b[i] = W_hh2[(size_t)(r * 8 + j) * 128 + k];
        }
    }
    if (tid < 4) sB2[tid] = b_ih2[tid * 128 + bid] + b_hh2[tid * 128 + bid];
    __syncthreads();

    unsigned ep = 0;
    for (int t = 0; t < 256; ++t) {
        // ---------- Phase A: lstm1 ----------
        {
            float acc[8];
#pragma unroll
            for (int a = 0; a < 8; a++) acc[a] = 0.f;
            int base = (ks * 4) * 256 + b * 4;
#pragma unroll
            for (int i = 0; i < 4; i++) {
                float4 s4 = __ldcg((const float4*)(g_ctx + base + i * 256));
                int kk = ks * 16 + i * 4;
#pragma unroll
                for (int rr = 0; rr < 4; rr++) {
                    float sr = (rr == 0) ? s4.x : (rr == 1) ? s4.y : (rr == 2) ? s4.z : s4.w;
                    const float* wp = sW1a + (size_t)(kk + rr) * 8;
                    float4 wA = *(const float4*)wp;
                    float4 wB = *(const float4*)(wp + 4);
                    acc[0] = fmaf(wA.x, sr, acc[0]); acc[1] = fmaf(wA.y, sr, acc[1]);
                    acc[2] = fmaf(wA.z, sr, acc[2]); acc[3] = fmaf(wA.w, sr, acc[3]);
                    acc[4] = fmaf(wB.x, sr, acc[4]); acc[5] = fmaf(wB.y, sr, acc[5]);
                    acc[6] = fmaf(wB.z, sr, acc[6]); acc[7] = fmaf(wB.w, sr, acc[7]);
                }
            }
#pragma unroll
            for (int a = 0; a < 8; a++) sP[ks * 512 + a * 64 + b] = acc[a];
        }
        __syncthreads();
        {
            int a = tid >> 6, b2 = tid & 63;
            int c = (a >> 1) * 256 + bid * 2 + (a & 1);
            float s = __ldcg(&g_Gpre[(size_t)t * 65536 + c * 64 + b2])
                    + __ldcg(&g_P1b[c * 64 + b2]);
#pragma unroll
            for (int k2 = 0; k2 < 8; k2++) s += sP[k2 * 512 + a * 64 + b2];
            sG[a * 64 + b2] = s;
        }
        __syncthreads();
        if (tid < 128) {
            int jl = tid >> 6, b2 = tid & 63;
            int j = bid * 2 + jl;
            float gi = sG[(0 + jl) * 64 + b2], gf = sG[(2 + jl) * 64 + b2];
            float gg = sG[(4 + jl) * 64 + b2], go = sG[(6 + jl) * 64 + b2];
            float cn = sigm(gf) * g_c1[j * 64 + b2] + sigm(gi) * ftanh(gg);
            float hn = sigm(go) * ftanh(cn);
            g_c1[j * 64 + b2] = cn;
            g_h1[(j >> 2) * 256 + b2 * 4 + (j & 3)] = hn;
        }
        gbar(++ep);
        // ---------- Phase B: lstm2 ----------
        {
            float acc[4] = {0.f, 0.f, 0.f, 0.f};
            int base = (ks * 8) * 256 + b * 4;
#pragma unroll
            for (int i = 0; i < 8; i++) {
                float4 s4 = __ldcg((const float4*)(g_h1 + base + i * 256));
                int kk = ks * 32 + i * 4;
#pragma unroll
                for (int rr = 0; rr < 4; rr++) {
                    float sr = (rr == 0) ? s4.x : (rr == 1) ? s4.y : (rr == 2) ? s4.z : s4.w;
                    float4 w = *(const float4*)(sW2a + (size_t)(kk + rr) * 4);
                    acc[0] = fmaf(w.x, sr, acc[0]); acc[1] = fmaf(w.y, sr, acc[1]);
                    acc[2] = fmaf(w.z, sr, acc[2]); acc[3] = fmaf(w.w, sr, acc[3]);
                }
            }
#pragma unroll
            for (int q = 0; q < 4; q++) sP[ks * 256 + q * 64 + b] = acc[q];
        }
        __syncthreads();
        if (tid < 256) {
            int q = tid >> 6, b2 = tid & 63;
            int c2 = q * 128 + bid;
            float s = sB2[q] + __ldcg(&g_P2b[c2 * 64 + b2]);
#pragma unroll
            for (int k2 = 0; k2 < 8; k2++) s += sP[k2 * 256 + q * 64 + b2];
            sG[q * 64 + b2] = s;
        }
        __syncthreads();
        if (tid < 64) {
            int b2 = tid;
            float gi = sG[0 * 64 + b2], gf = sG[1 * 64 + b2];
            float gg = sG[2 * 64 + b2], go = sG[3 * 64 + b2];
            float cn = sigm(gf) * g_c2[bid * 64 + b2] + sigm(gi) * ftanh(gg);
            float hn = sigm(go) * ftanh(cn);
            g_c2[bid * 64 + b2] = cn;
            g_h2[(bid >> 2) * 256 + b2 * 4 + (bid & 3)] = hn;
            g_AllT[(size_t)t * 16384 + bid * 64 + b2] = hn;
        }
        gbar(++ep);
        // ---------- Phase C ----------
        if (bid < 64) {
            // attention, one batch row per block
            const int b3 = bid;
            if (tid < 128)
                sH2f[tid] = __ldcg(&g_h2[(tid >> 2) * 256 + b3 * 4 + (tid & 3)]);
            __syncthreads();
            {
                const float4* sH2v4 = (const float4*)sH2f;
                int ch = lane & 7, rsub = lane >> 3;
                float4 h0 = sH2v4[ch], h1v = sH2v4[ch + 8], h2v = sH2v4[ch + 16], h3v = sH2v4[ch + 24];
                const float4* kbase = (const float4*)(key + (size_t)b3 * 512 * 128);
#pragma unroll
                for (int j = 0; j < 8; j++) {
                    int row = wrp * 32 + j * 4 + rsub;
                    const float4* kp = kbase + (size_t)row * 32;
                    float4 k0 = __ldg(kp + ch), k1 = __ldg(kp + ch + 8);
                    float4 k2 = __ldg(kp + ch + 16), k3 = __ldg(kp + ch + 24);
                    float e = k0.x * h0.x;
                    e = fmaf(k0.y, h0.y, e); e = fmaf(k0.z, h0.z, e); e = fmaf(k0.w, h0.w, e);
                    e = fmaf(k1.x, h1v.x, e); e = fmaf(k1.y, h1v.y, e); e = fmaf(k1.z, h1v.z, e); e = fmaf(k1.w, h1v.w, e);
                    e = fmaf(k2.x, h2v.x, e); e = fmaf(k2.y, h2v.y, e); e = fmaf(k2.z, h2v.z, e); e = fmaf(k2.w, h2v.w, e);
                    e = fmaf(k3.x, h3v.x, e); e = fmaf(k3.y, h3v.y, e); e = fmaf(k3.z, h3v.z, e); e = fmaf(k3.w, h3v.w, e);
                    e += __shfl_xor_sync(0xffffffffu, e, 4);
                    e += __shfl_xor_sync(0xffffffffu, e, 2);
                    e += __shfl_xor_sync(0xffffffffu, e, 1);
                    if (ch == 0) sEn[row] = e;
                }
            }
            __syncthreads();
            float e = sEn[tid];
            float m = e;
#pragma unroll
            for (int off = 16; off > 0; off >>= 1) m = fmaxf(m, __shfl_xor_sync(0xffffffffu, m, off));
            if (lane == 0) sRed[wrp] = m;
            __syncthreads();
            if (tid < 32) {
                float mm = (tid < 16) ? sRed[tid] : -3.402823466e38f;
#pragma unroll
                for (int off = 8; off > 0; off >>= 1) mm = fmaxf(mm, __shfl_xor_sync(0xffffffffu, mm, off));
                if (tid == 0) sRed[16] = mm;
            }
            __syncthreads();
            float mx = sRed[16];
            float ex = __expf(e - mx);
            sEn[tid] = ex;
            float ssum = ex;
#pragma unroll
            for (int off = 16; off > 0; off >>= 1) ssum += __shfl_xor_sync(0xffffffffu, ssum, off);
            if (lane == 0) sRed[wrp] = ssum;
            __syncthreads();
            if (tid < 32) {
                float tt = (tid < 16) ? sRed[tid] : 0.f;
#pragma unroll
                for (int off = 8; off > 0; off >>= 1) tt += __shfl_xor_sync(0xffffffffu, tt, off);
                if (tid == 0) sRed[17] = tt;
            }
            __syncthreads();
            {
                int v4 = tid & 31, g = tid >> 5;
                const float* vb = values + (size_t)b3 * 65536 + v4 * 4;
                float4 a4 = make_float4(0.f, 0.f, 0.f, 0.f);
#pragma unroll 8
                for (int i = 0; i < 32; i++) {
                    int tp = g * 32 + i;
                    float wgt = sEn[tp];
                    float4 vv = __ldg((const float4*)(vb + (size_t)tp * 128));
                    a4.x = fmaf(wgt, vv.x, a4.x); a4.y = fmaf(wgt, vv.y, a4.y);
                    a4.z = fmaf(wgt, vv.z, a4.z); a4.w = fmaf(wgt, vv.w, a4.w);
                }
                ((float4*)(sVal + g * 128))[v4] = a4;
            }
            __syncthreads();
            if (tid < 128) {
                float s = 0.f;
#pragma unroll
                for (int g2 = 0; g2 < 16; g2++) s += sVal[g2 * 128 + tid];
                float cv = s / sRed[17];
                g_ctx[(tid >> 2) * 256 + b3 * 4 + (tid & 3)] = cv;
                g_AllT[(size_t)t * 16384 + (128 + tid) * 64 + b3] = cv;
            }
        } else {
            // next-step recurrent partials
            const int r = bid - 64;
#pragma unroll
            for (int h = 0; h < 2; h++) {
                float acc[8];
#pragma unroll
                for (int j = 0; j < 8; j++) acc[j] = 0.f;
                int base = (ks * 8) * 256 + b * 4;
#pragma unroll
                for (int i = 0; i < 8; i++) {
                    float4 s4 = __ldcg((const float4*)(g_h1 + base + i * 256));
                    int kk = ks * 32 + i * 4;
#pragma unroll
                    for (int rr = 0; rr < 4; rr++) {
                        float sr = (rr == 0) ? s4.x : (rr == 1) ? s4.y : (rr == 2) ? s4.z : s4.w;
                        const float* wp = sW1b + (size_t)(kk + rr) * 16 + h * 8;
                        float4 w0 = *(const float4*)wp;
                        float4 w1 = *(const float4*)(wp + 4);
                        acc[0] = fmaf(w0.x, sr, acc[0]); acc[1] = fmaf(w0.y, sr, acc[1]);
                        acc[2] = fmaf(w0.z, sr, acc[2]); acc[3] = fmaf(w0.w, sr, acc[3]);
                        acc[4] = fmaf(w1.x, sr, acc[4]); acc[5] = fmaf(w1.y, sr, acc[5]);
                        acc[6] = fmaf(w1.z, sr, acc[6]); acc[7] = fmaf(w1.w, sr, acc[7]);
                    }
                }
#pragma unroll
                for (int j = 0; j < 8; j++) sP[ks * 512 + j * 64 + b] = acc[j];
                __syncthreads();
                {
                    int j = tid >> 6, b2 = tid & 63;
                    float s = 0.f;
#pragma unroll
                    for (int k2 = 0; k2 < 8; k2++) s += sP[k2 * 512 + j * 64 + b2];
                    g_P1b[(r * 16 + h * 8 + j) * 64 + b2] = s;
                }
                __syncthreads();
            }
            {
                float acc2[8];
#pragma unroll
                for (int j = 0; j < 8; j++) acc2[j] = 0.f;
                int base2 = (ks * 4) * 256 + b * 4;
#pragma unroll
                for (int i = 0; i < 4; i++) {
                    float4 s4 = __ldcg((const float4*)(g_h2 + base2 + i * 256));
                    int kk = ks * 16 + i * 4;
#pragma unroll
                    for (int rr = 0; rr < 4; rr++) {
                        float sr = (rr == 0) ? s4.x : (rr == 1) ? s4.y : (rr == 2) ? s4.z : s4.w;
                        const float* wp = sW2b + (size_t)(kk + rr) * 8;
                        float4 w0 = *(const float4*)wp;
                        float4 w1 = *(const float4*)(wp + 4);
                        acc2[0] = fmaf(w0.x, sr, acc2[0]); acc2[1] = fmaf(w0.y, sr, acc2[1]);
                        acc2[2] = fmaf(w0.z, sr, acc2[2]); acc2[3] = fmaf(w0.w, sr, acc2[3]);
                        acc2[4] = fmaf(w1.x, sr, acc2[4]); acc2[5] = fmaf(w1.y, sr, acc2[5]);
                        acc2[6] = fmaf(w1.z, sr, acc2[6]); acc2[7] = fmaf(w1.w, sr, acc2[7]);
                    }
                }
#pragma unroll
                for (int j = 0; j < 8; j++) sP[ks * 512 + j * 64 + b] = acc2[j];
                __syncthreads();
                {
                    int j = tid >> 6, b2 = tid & 63;
                    float s = 0.f;
#pragma unroll
                    for (int k2 = 0; k2 < 8; k2++) s += sP[k2 * 512 + j * 64 + b2];
                    g_P2b[(r * 8 + j) * 64 + b2] = s;
                }
            }
        }
        gbar(++ep);
    }
}

// ------------------------- kernel 3: logits = AllT^T @ ET + b_out -------------------------
__global__ void __launch_bounds__(256) logits_k(const float* __restrict__ b_out,
                                                float* __restrict__ out) {
    __shared__ __align__(16) float sX[16 * 64];
    __shared__ __align__(16) float sE[16 * 128];
    const int v0 = blockIdx.x * 128;
    const int t = blockIdx.y;
    const int tid = threadIdx.x;
    const int vx = tid & 31, bx = tid >> 5;
    float4 acc[8];
#pragma unroll
    for (int i = 0; i < 8; i++) acc[i] = make_float4(0, 0, 0, 0);

    const int kl = tid >> 4, bq = tid & 15;
    const int ke = tid >> 5, ve = tid & 31;

    for (int c0 = 0; c0 < 256; c0 += 16) {
        float4 xv = *(const float4*)(g_AllT + (size_t)t * 16384 + (size_t)(c0 + kl) * 64 + bq * 4);
        float4 e0 = *(const float4*)(g_ET + (size_t)(c0 + ke) * 4096 + v0 + ve * 4);
        float4 e1 = *(const float4*)(g_ET + (size_t)(c0 + ke + 8) * 4096 + v0 + ve * 4);
        __syncthreads();
        *(float4*)&sX[kl * 64 + bq * 4] = xv;
        *(float4*)&sE[ke * 128 + ve * 4] = e0;
        *(float4*)&sE[(ke + 8) * 128 + ve * 4] = e1;
        __syncthreads();
#pragma unroll
        for (int k = 0; k < 16; k++) {
            float4 ev = *(const float4*)&sE[k * 128 + vx * 4];
            float4 x0 = *(const float4*)&sX[k * 64 + bx * 8];
            float4 x1 = *(const float4*)&sX[k * 64 + bx * 8 + 4];
            float xs[8] = {x0.x, x0.y, x0.z, x0.w, x1.x, x1.y, x1.z, x1.w};
#pragma unroll
            for (int j = 0; j < 8; j++) {
                acc[j].x = fmaf(xs[j], ev.x, acc[j].x);
                acc[j].y = fmaf(xs[j], ev.y, acc[j].y);
                acc[j].z = fmaf(xs[j], ev.z, acc[j].z);
                acc[j].w = fmaf(xs[j], ev.w, acc[j].w);
            }
        }
    }
    float4 bo = *(const float4*)(b_out + v0 + vx * 4);
#pragma unroll
    for (int j = 0; j < 8; j++) {
        int bb = bx * 8 + j;
        float4 r = make_float4(acc[j].x + bo.x, acc[j].y + bo.y,
                               acc[j].z + bo.z, acc[j].w + bo.w);
        *(float4*)(out + ((size_t)bb * 256 + t) * 4096 + v0 + vx * 4) = r;
    }
}

// ------------------------- launch -------------------------
extern "C" void kernel_launch(void* const* d_in, const int* in_sizes, int n_in,
                              void* d_out, int out_size) {
    (void)in_sizes; (void)n_in; (void)out_size;
    const float* key    = (const float*)d_in[0];
    const float* values = (const float*)d_in[1];
    const int*   text   = (const int*)d_in[3];
    const float* E      = (const float*)d_in[4];
    const float* W_ih1  = (const float*)d_in[5];
    const float* W_hh1  = (const float*)d_in[6];
    const float* b_ih1  = (const float*)d_in[7];
    const float* b_hh1  = (const float*)d_in[8];
    const float* W_ih2  = (const float*)d_in[9];
    const float* W_hh2  = (const float*)d_in[10];
    const float* b_ih2  = (const float*)d_in[11];
    const float* b_hh2  = (const float*)d_in[12];
    const float* b_out  = (const float*)d_in[13];
    float*       out    = (float*)d_out;

    prep_k<<<128, 256>>>();
    ew_k<<<dim3(16, 64), 256>>>(E, W_ih1, b_ih1, b_hh1);
    gpre_k<<<256, 512>>>(text);
    et_k<<<dim3(128, 8), 256>>>(E);
    recur_k<<<NBLK, NTHR>>>(key, values, W_ih1, W_hh1, W_ih2, W_hh2, b_ih2, b_hh2);
    logits_k<<<dim3(32, 256), 256>>>(b_out, out);
}

// round 9
// speedup vs baseline: 1.1339x; 1.1339x over previous
#include <cuda_runtime.h>
#include <cstdint>
#include <cstddef>
#include <math.h>

#define NBLK 128
#define NTHR 512
#define KSM_FLOATS (256 * 128)
#define KSM_BYTES  (KSM_FLOATS * 4)

// ------------------------- device scratch (static, no allocs) -------------------------
__device__ float    g_EW[4096u * 1024u];        // [row][c]: E@W_ih1[:, :256]^T + b_ih1 + b_hh1
__device__ float    g_Gpre[256u * 1024u * 64u]; // [t][c][b]: embedding gate bias per step
__device__ float    g_AllT[256u * 256u * 64u];  // [t][c][b], c<128 h2, c>=128 ctx
__device__ float    g_ET[256u * 4096u];         // E transposed: [c][v]
// state, k-major packed: idx(k,b) = (k>>2)*256 + b*4 + (k&3)
__device__ float    g_S1v[2][96 * 256];         // lstm1 input: k<128 ctx, k in [128,384) h1
__device__ float    g_S2v[2][96 * 256];         // lstm2 input: k<256 h1, k in [256,384) h2
__device__ float    g_c1[256 * 64];
__device__ float    g_c2[128 * 64];
__device__ float    g_attP[64][128];            // upper-half attention value partials
__device__ float    g_attMS[64][2];             // upper-half (max, sum)
__device__ unsigned g_pf[64];                   // pair flags
__device__ unsigned g_slots[NBLK];

__device__ __forceinline__ float sigm(float x) { return 1.0f / (1.0f + __expf(-x)); }
__device__ __forceinline__ float ftanh(float x) {
    float cx = fminf(fmaxf(x, -15.f), 15.f);
    float e = __expf(2.f * cx);
    return (e - 1.f) / (e + 1.f);
}

// Atomic-free grid barrier.
__device__ __forceinline__ void gbar(unsigned epoch) {
    __syncthreads();
    if (threadIdx.x == 0) {
        __threadfence();
        asm volatile("st.release.gpu.u32 [%0], %1;"
                     :: "l"(&g_slots[blockIdx.x]), "r"(epoch) : "memory");
    }
    bool ok;
    do {
        unsigned v = epoch;
        if (threadIdx.x < NBLK)
            asm volatile("ld.acquire.gpu.u32 %0, [%1];"
                         : "=r"(v) : "l"(&g_slots[threadIdx.x]) : "memory");
        ok = (v >= epoch);
    } while (!__syncthreads_and((int)ok));
}

// ------------------------- kernel 0: zero state -------------------------
__global__ void prep_k() {
    int i0 = blockIdx.x * blockDim.x + threadIdx.x;
    int st = gridDim.x * blockDim.x;
    for (int i = i0; i < 96 * 256; i += st) {
        g_S1v[0][i] = 0.f; g_S1v[1][i] = 0.f;
        g_S2v[0][i] = 0.f; g_S2v[1][i] = 0.f;
    }
    for (int i = i0; i < 256 * 64; i += st) g_c1[i] = 0.f;
    for (int i = i0; i < 128 * 64; i += st) g_c2[i] = 0.f;
    if (i0 < NBLK) g_slots[i0] = 0u;
    if (i0 < 64) g_pf[i0] = 0u;
}

// ------------------------- kernel 1: EW[v][c] = E[v,:] . W_ih1[c, :256] + bias -------------------------
__global__ void __launch_bounds__(256) ew_k(const float* __restrict__ E,
                                            const float* __restrict__ W_ih1,
                                            const float* __restrict__ b_ih1,
                                            const float* __restrict__ b_hh1) {
    __shared__ __align__(16) float sA[16][68];
    __shared__ __align__(16) float sB[16][68];
    const int c0 = blockIdx.x * 64, v0 = blockIdx.y * 64;
    const int tid = threadIdx.x;
    const int lw = tid >> 2, kq = tid & 3;
    const int cx = tid & 15, vxx = tid >> 4;
    float4 acc[4];
    acc[0] = acc[1] = acc[2] = acc[3] = make_float4(0, 0, 0, 0);
    for (int k0 = 0; k0 < 256; k0 += 16) {
        float4 av = *(const float4*)(E + (size_t)(v0 + lw) * 256 + k0 + kq * 4);
        float4 bv = *(const float4*)(W_ih1 + (size_t)(c0 + lw) * 384 + k0 + kq * 4);
        __syncthreads();
        sA[kq * 4 + 0][lw] = av.x; sA[kq * 4 + 1][lw] = av.y;
        sA[kq * 4 + 2][lw] = av.z; sA[kq * 4 + 3][lw] = av.w;
        sB[kq * 4 + 0][lw] = bv.x; sB[kq * 4 + 1][lw] = bv.y;
        sB[kq * 4 + 2][lw] = bv.z; sB[kq * 4 + 3][lw] = bv.w;
        __syncthreads();
#pragma unroll
        for (int k = 0; k < 16; k++) {
            float4 cv = *(const float4*)&sB[k][cx * 4];
            float4 vv = *(const float4*)&sA[k][vxx * 4];
            float vs[4] = {vv.x, vv.y, vv.z, vv.w};
#pragma unroll
            for (int vi = 0; vi < 4; vi++) {
                acc[vi].x = fmaf(vs[vi], cv.x, acc[vi].x);
                acc[vi].y = fmaf(vs[vi], cv.y, acc[vi].y);
                acc[vi].z = fmaf(vs[vi], cv.z, acc[vi].z);
                acc[vi].w = fmaf(vs[vi], cv.w, acc[vi].w);
            }
        }
    }
    float4 bi = *(const float4*)(b_ih1 + c0 + cx * 4);
    float4 bh = *(const float4*)(b_hh1 + c0 + cx * 4);
    float4 bias = make_float4(bi.x + bh.x, bi.y + bh.y, bi.z + bh.z, bi.w + bh.w);
#pragma unroll
    for (int vi = 0; vi < 4; vi++) {
        float4 r = make_float4(acc[vi].x + bias.x, acc[vi].y + bias.y,
                               acc[vi].z + bias.z, acc[vi].w + bias.w);
        *(float4*)(g_EW + (size_t)(v0 + vxx * 4 + vi) * 1024 + c0 + cx * 4) = r;
    }
}

// ------------------------- kernel 1b: Gpre[t][c][b] = EW[text[b][t]][c] -------------------------
__global__ void __launch_bounds__(512) gpre_k(const int* __restrict__ text) {
    const int t = blockIdx.x;
    const int tid = threadIdx.x;
    const int b = tid & 63, cs = tid >> 6;
    const int row = text[b * 256 + t] & 4095;
    const float* src = g_EW + (size_t)row * 1024;
    float* dst = g_Gpre + (size_t)t * 65536;
    for (int c = cs; c < 1024; c += 8)
        dst[c * 64 + b] = src[c];
}

// ------------------------- kernel 1c: ET[c][v] = E[v][c] -------------------------
__global__ void __launch_bounds__(256) et_k(const float* __restrict__ E) {
    __shared__ float sT[32][33];
    const int v0 = blockIdx.x * 32, c0 = blockIdx.y * 32;
    const int tx = threadIdx.x & 31, ty = threadIdx.x >> 5;
#pragma unroll
    for (int i = 0; i < 4; i++)
        sT[ty + i * 8][tx] = E[(size_t)(v0 + ty + i * 8) * 256 + c0 + tx];
    __syncthreads();
#pragma unroll
    for (int i = 0; i < 4; i++)
        g_ET[(size_t)(c0 + ty + i * 8) * 4096 + v0 + tx] = sT[tx][ty + i * 8];
}

// ------------------------- kernel 2: persistent recurrence -------------------------
// Block pair (b, b+64) handles batch b's attention T-halves; K half resident in SMEM.
__global__ void __launch_bounds__(NTHR, 1) recur_k(
    const float* __restrict__ key, const float* __restrict__ values,
    const float* __restrict__ W_ih1, const float* __restrict__ W_hh1,
    const float* __restrict__ W_ih2, const float* __restrict__ W_hh2,
    const float* __restrict__ b_ih2, const float* __restrict__ b_hh2) {
    extern __shared__ __align__(16) float Ksm[];    // [256][128] K half tile (row = 512B)
    __shared__ __align__(16) float sW1v[384 * 8];   // [k][a], a = gate*2 + jl
    __shared__ __align__(16) float sW2v[384 * 4];   // [k][q]
    __shared__ __align__(16) float sP[4096];        // partials / attention scratch
    __shared__ float sG[8 * 64];
    __shared__ float sB2[4];

    float* sEn  = sP;          // [256] energies/weights
    float* sVal = sP + 256;    // [16*128]
    float* sH2f = sP + 2304;   // [128]
    float* sRed = sP + 2432;   // [32]
    float* sMS  = sP + 2464;   // m, s

    const int tid = threadIdx.x;
    const int bid = blockIdx.x;
    const int b = tid & 63, ks = tid >> 6;
    const int lane = tid & 31, wrp = tid >> 5;
    const int b3 = bid & 63, thalf = bid >> 6;

    // ---- weight staging (k-major) ----
    for (int i = tid; i < 384 * 8; i += NTHR) {
        int k = i >> 3, a = i & 7;
        int c = (a >> 1) * 256 + bid * 2 + (a & 1);
        sW1v[i] = (k < 128) ? W_ih1[(size_t)c * 384 + 256 + k]
                            : W_hh1[(size_t)c * 256 + (k - 128)];
    }
    for (int i = tid; i < 384 * 4; i += NTHR) {
        int k = i >> 2, q = i & 3;
        int c2 = q * 128 + bid;
        sW2v[i] = (k < 256) ? W_ih2[(size_t)c2 * 256 + k]
                            : W_hh2[(size_t)c2 * 128 + (k - 256)];
    }
    if (tid < 4) sB2[tid] = b_ih2[tid * 128 + bid] + b_hh2[tid * 128 + bid];
    // ---- K tile into SMEM (once): rows thalf*256..+256 of batch b3 ----
    {
        const float4* ksrc = (const float4*)(key + ((size_t)b3 * 512 + thalf * 256) * 128);
        float4* kdst = (float4*)Ksm;
        for (int i = tid; i < 256 * 32; i += NTHR)
            kdst[i] = ksrc[i];
    }
    __syncthreads();

    unsigned ep = 0;
    for (int t = 0; t < 256; ++t) {
        const int rd = t & 1, wr = rd ^ 1;
        // ---------- P1: lstm1 ----------
        {
            const float* Sv = g_S1v[rd];
            float acc[8];
#pragma unroll
            for (int a = 0; a < 8; a++) acc[a] = 0.f;
            int base = (ks * 12) * 256 + b * 4;
#pragma unroll
            for (int i = 0; i < 12; i++) {
                float4 s4 = __ldcg((const float4*)(Sv + base + i * 256));
                int kk = (ks * 12 + i) * 4;
#pragma unroll
                for (int r = 0; r < 4; r++) {
                    float sr = (r == 0) ? s4.x : (r == 1) ? s4.y : (r == 2) ? s4.z : s4.w;
                    const float* wp = sW1v + (size_t)(kk + r) * 8;
                    float4 wA = *(const float4*)wp;
                    float4 wB = *(const float4*)(wp + 4);
                    acc[0] = fmaf(wA.x, sr, acc[0]); acc[1] = fmaf(wA.y, sr, acc[1]);
                    acc[2] = fmaf(wA.z, sr, acc[2]); acc[3] = fmaf(wA.w, sr, acc[3]);
                    acc[4] = fmaf(wB.x, sr, acc[4]); acc[5] = fmaf(wB.y, sr, acc[5]);
                    acc[6] = fmaf(wB.z, sr, acc[6]); acc[7] = fmaf(wB.w, sr, acc[7]);
                }
            }
#pragma unroll
            for (int a = 0; a < 8; a++) sP[ks * 512 + a * 64 + b] = acc[a];
        }
        __syncthreads();
        {
            int a = tid >> 6, b2 = tid & 63;
            int c = (a >> 1) * 256 + bid * 2 + (a & 1);
            float s = __ldcg(&g_Gpre[(size_t)t * 65536 + c * 64 + b2]);
#pragma unroll
            for (int k2 = 0; k2 < 8; k2++) s += sP[k2 * 512 + a * 64 + b2];
            sG[a * 64 + b2] = s;
        }
        __syncthreads();
        if (tid < 128) {
            int jl = tid >> 6, b2 = tid & 63;
            int j = bid * 2 + jl;
            float gi = sG[(0 + jl) * 64 + b2], gf = sG[(2 + jl) * 64 + b2];
            float gg = sG[(4 + jl) * 64 + b2], go = sG[(6 + jl) * 64 + b2];
            float cn = sigm(gf) * g_c1[j * 64 + b2] + sigm(gi) * ftanh(gg);
            float hn = sigm(go) * ftanh(cn);
            g_c1[j * 64 + b2] = cn;
            int k1 = 128 + j;
            g_S1v[wr][(k1 >> 2) * 256 + b2 * 4 + (k1 & 3)] = hn;
            g_S2v[rd][(j >> 2) * 256 + b2 * 4 + (j & 3)] = hn;
        }
        gbar(++ep);
        // ---------- P2: lstm2 ----------
        {
            const float* Sv = g_S2v[rd];
            float acc[4] = {0.f, 0.f, 0.f, 0.f};
            int base = (ks * 12) * 256 + b * 4;
#pragma unroll
            for (int i = 0; i < 12; i++) {
                float4 s4 = __ldcg((const float4*)(Sv + base + i * 256));
                int kk = (ks * 12 + i) * 4;
#pragma unroll
                for (int r = 0; r < 4; r++) {
                    float sr = (r == 0) ? s4.x : (r == 1) ? s4.y : (r == 2) ? s4.z : s4.w;
                    float4 w = *(const float4*)(sW2v + (size_t)(kk + r) * 4);
                    acc[0] = fmaf(w.x, sr, acc[0]); acc[1] = fmaf(w.y, sr, acc[1]);
                    acc[2] = fmaf(w.z, sr, acc[2]); acc[3] = fmaf(w.w, sr, acc[3]);
                }
            }
#pragma unroll
            for (int q = 0; q < 4; q++) sP[ks * 256 + q * 64 + b] = acc[q];
        }
        __syncthreads();
        if (tid < 256) {
            int q = tid >> 6, b2 = tid & 63;
            float s = sB2[q];
#pragma unroll
            for (int k2 = 0; k2 < 8; k2++) s += sP[k2 * 256 + q * 64 + b2];
            sG[q * 64 + b2] = s;
        }
        __syncthreads();
        if (tid < 64) {
            int b2 = tid;
            float gi = sG[0 * 64 + b2], gf = sG[1 * 64 + b2];
            float gg = sG[2 * 64 + b2], go = sG[3 * 64 + b2];
            float cn = sigm(gf) * g_c2[bid * 64 + b2] + sigm(gi) * ftanh(gg);
            float hn = sigm(go) * ftanh(cn);
            g_c2[bid * 64 + b2] = cn;
            int k2i = 256 + bid;
            g_S2v[wr][(k2i >> 2) * 256 + b2 * 4 + (k2i & 3)] = hn;
            g_AllT[(size_t)t * 16384 + bid * 64 + b2] = hn;
        }
        gbar(++ep);
        // ---------- P3: split-T attention, all 128 blocks ----------
        {
            if (tid < 128) {
                int k = 256 + tid;
                sH2f[tid] = __ldcg(&g_S2v[wr][(k >> 2) * 256 + b3 * 4 + (k & 3)]);
            }
            __syncthreads();
            // energies from SMEM K (row stride 128 floats: aligned, conflict-free)
            {
                const float4* sH2v4 = (const float4*)sH2f;
                int ch = lane & 7, rsub = lane >> 3;
                float4 h0 = sH2v4[ch], h1v = sH2v4[ch + 8], h2v = sH2v4[ch + 16], h3v = sH2v4[ch + 24];
#pragma unroll
                for (int j = 0; j < 4; j++) {
                    int row = wrp * 16 + j * 4 + rsub;
                    const float* kp = Ksm + row * 128;
                    float4 k0 = *(const float4*)(kp + ch * 4);
                    float4 k1 = *(const float4*)(kp + (ch + 8) * 4);
                    float4 k2 = *(const float4*)(kp + (ch + 16) * 4);
                    float4 k3 = *(const float4*)(kp + (ch + 24) * 4);
                    float e = k0.x * h0.x;
                    e = fmaf(k0.y, h0.y, e); e = fmaf(k0.z, h0.z, e); e = fmaf(k0.w, h0.w, e);
                    e = fmaf(k1.x, h1v.x, e); e = fmaf(k1.y, h1v.y, e); e = fmaf(k1.z, h1v.z, e); e = fmaf(k1.w, h1v.w, e);
                    e = fmaf(k2.x, h2v.x, e); e = fmaf(k2.y, h2v.y, e); e = fmaf(k2.z, h2v.z, e); e = fmaf(k2.w, h2v.w, e);
                    e = fmaf(k3.x, h3v.x, e); e = fmaf(k3.y, h3v.y, e); e = fmaf(k3.z, h3v.z, e); e = fmaf(k3.w, h3v.w, e);
                    e += __shfl_xor_sync(0xffffffffu, e, 4);
                    e += __shfl_xor_sync(0xffffffffu, e, 2);
                    e += __shfl_xor_sync(0xffffffffu, e, 1);
                    if (ch == 0) sEn[row] = e;
                }
            }
            __syncthreads();
            // local softmax (unnormalized) over 256, 16 warp partials
            float e = (tid < 256) ? sEn[tid] : -3.402823466e38f;
            float m = e;
#pragma unroll
            for (int off = 16; off > 0; off >>= 1) m = fmaxf(m, __shfl_xor_sync(0xffffffffu, m, off));
            if (lane == 0) sRed[wrp] = m;
            __syncthreads();
            if (tid < 32) {
                float mm = (tid < 16) ? sRed[tid] : -3.402823466e38f;
#pragma unroll
                for (int off = 8; off > 0; off >>= 1) mm = fmaxf(mm, __shfl_xor_sync(0xffffffffu, mm, off));
                if (tid == 0) sMS[0] = mm;
            }
            __syncthreads();
            float mx = sMS[0];
            float w = (tid < 256) ? __expf(e - mx) : 0.f;
            if (tid < 256) sEn[tid] = w;
            float ssum = w;
#pragma unroll
            for (int off = 16; off > 0; off >>= 1) ssum += __shfl_xor_sync(0xffffffffu, ssum, off);
            if (lane == 0) sRed[wrp] = ssum;
            __syncthreads();
            if (tid < 32) {
                float tt = (tid < 16) ? sRed[tid] : 0.f;
#pragma unroll
                for (int off = 8; off > 0; off >>= 1) tt += __shfl_xor_sync(0xffffffffu, tt, off);
                if (tid == 0) sMS[1] = tt;
            }
            __syncthreads();
            // weighted V partial (unnormalized): rows thalf*256 + [0,256)
            {
                int v4 = tid & 31, g = tid >> 5;
                const float* vb = values + ((size_t)b3 * 512 + thalf * 256) * 128 + v4 * 4;
                float4 a4 = make_float4(0.f, 0.f, 0.f, 0.f);
#pragma unroll 8
                for (int i = 0; i < 16; i++) {
                    int tp = g * 16 + i;
                    float wgt = sEn[tp];
                    float4 vv = __ldg((const float4*)(vb + (size_t)tp * 128));
                    a4.x = fmaf(wgt, vv.x, a4.x); a4.y = fmaf(wgt, vv.y, a4.y);
                    a4.z = fmaf(wgt, vv.z, a4.z); a4.w = fmaf(wgt, vv.w, a4.w);
                }
                ((float4*)(sVal + g * 128))[v4] = a4;
            }
            __syncthreads();
            float p0 = 0.f;
            if (tid < 128) {
#pragma unroll
                for (int g2 = 0; g2 < 16; g2++) p0 += sVal[g2 * 128 + tid];
            }
            if (thalf == 1) {
                // publish partials, signal pair
                if (tid < 128) g_attP[b3][tid] = p0;
                if (tid == 0) { g_attMS[b3][0] = sMS[0]; g_attMS[b3][1] = sMS[1]; }
                __syncthreads();
                if (tid == 0) {
                    __threadfence();
                    asm volatile("st.release.gpu.u32 [%0], %1;"
                                 :: "l"(&g_pf[b3]), "r"((unsigned)(t + 1)) : "memory");
                }
            } else {
                // wait for peer, combine, write ctx
                if (tid == 0) {
                    unsigned v;
                    do {
                        asm volatile("ld.acquire.gpu.u32 %0, [%1];"
                                     : "=r"(v) : "l"(&g_pf[b3]) : "memory");
                    } while (v < (unsigned)(t + 1));
                }
                __syncthreads();
                if (tid < 128) {
                    float m0 = sMS[0], s0 = sMS[1];
                    float m1 = __ldcg(&g_attMS[b3][0]), s1 = __ldcg(&g_attMS[b3][1]);
                    float p1 = __ldcg(&g_attP[b3][tid]);
                    float M = fmaxf(m0, m1);
                    float a0 = __expf(m0 - M), a1 = __expf(m1 - M);
                    float cv = (p0 * a0 + p1 * a1) / (s0 * a0 + s1 * a1);
                    g_S1v[wr][(tid >> 2) * 256 + b3 * 4 + (tid & 3)] = cv;
                    g_AllT[(size_t)t * 16384 + (128 + tid) * 64 + b3] = cv;
                }
            }
        }
        gbar(++ep);
    }
}

// ------------------------- kernel 3: logits = AllT^T @ ET + b_out -------------------------
__global__ void __launch_bounds__(256) logits_k(const float* __restrict__ b_out,
                                                float* __restrict__ out) {
    __shared__ __align__(16) float sX[16 * 64];
    __shared__ __align__(16) float sE[16 * 128];
    const int v0 = blockIdx.x * 128;
    const int t = blockIdx.y;
    const int tid = threadIdx.x;
    const int vx = tid & 31, bx = tid >> 5;
    float4 acc[8];
#pragma unroll
    for (int i = 0; i < 8; i++) acc[i] = make_float4(0, 0, 0, 0);

    const int kl = tid >> 4, bq = tid & 15;
    const int ke = tid >> 5, ve = tid & 31;

    for (int c0 = 0; c0 < 256; c0 += 16) {
        float4 xv = *(const float4*)(g_AllT + (size_t)t * 16384 + (size_t)(c0 + kl) * 64 + bq * 4);
        float4 e0 = *(const float4*)(g_ET + (size_t)(c0 + ke) * 4096 + v0 + ve * 4);
        float4 e1 = *(const float4*)(g_ET + (size_t)(c0 + ke + 8) * 4096 + v0 + ve * 4);
        __syncthreads();
        *(float4*)&sX[kl * 64 + bq * 4] = xv;
        *(float4*)&sE[ke * 128 + ve * 4] = e0;
        *(float4*)&sE[(ke + 8) * 128 + ve * 4] = e1;
        __syncthreads();
#pragma unroll
        for (int k = 0; k < 16; k++) {
            float4 ev = *(const float4*)&sE[k * 128 + vx * 4];
            float4 x0 = *(const float4*)&sX[k * 64 + bx * 8];
            float4 x1 = *(const float4*)&sX[k * 64 + bx * 8 + 4];
            float xs[8] = {x0.x, x0.y, x0.z, x0.w, x1.x, x1.y, x1.z, x1.w};
#pragma unroll
            for (int j = 0; j < 8; j++) {
                acc[j].x = fmaf(xs[j], ev.x, acc[j].x);
                acc[j].y = fmaf(xs[j], ev.y, acc[j].y);
                acc[j].z = fmaf(xs[j], ev.z, acc[j].z);
                acc[j].w = fmaf(xs[j], ev.w, acc[j].w);
            }
        }
    }
    float4 bo = *(const float4*)(b_out + v0 + vx * 4);
#pragma unroll
    for (int j = 0; j < 8; j++) {
        int bb = bx * 8 + j;
        float4 r = make_float4(acc[j].x + bo.x, acc[j].y + bo.y,
                               acc[j].z + bo.z, acc[j].w + bo.w);
        *(float4*)(out + ((size_t)bb * 256 + t) * 4096 + v0 + vx * 4) = r;
    }
}

// ------------------------- launch -------------------------
extern "C" void kernel_launch(void* const* d_in, const int* in_sizes, int n_in,
                              void* d_out, int out_size) {
    (void)in_sizes; (void)n_in; (void)out_size;
    const float* key    = (const float*)d_in[0];
    const float* values = (const float*)d_in[1];
    const int*   text   = (const int*)d_in[3];
    const float* E      = (const float*)d_in[4];
    const float* W_ih1  = (const float*)d_in[5];
    const float* W_hh1  = (const float*)d_in[6];
    const float* b_ih1  = (const float*)d_in[7];
    const float* b_hh1  = (const float*)d_in[8];
    const float* W_ih2  = (const float*)d_in[9];
    const float* W_hh2  = (const float*)d_in[10];
    const float* b_ih2  = (const float*)d_in[11];
    const float* b_hh2  = (const float*)d_in[12];
    const float* b_out  = (const float*)d_in[13];
    float*       out    = (float*)d_out;

    cudaFuncSetAttribute(recur_k, cudaFuncAttributeMaxDynamicSharedMemorySize, KSM_BYTES);

    prep_k<<<128, 256>>>();
    ew_k<<<dim3(16, 64), 256>>>(E, W_ih1, b_ih1, b_hh1);
    gpre_k<<<256, 512>>>(text);
    et_k<<<dim3(128, 8), 256>>>(E);
    recur_k<<<NBLK, NTHR, KSM_BYTES>>>(key, values, W_ih1, W_hh1, W_ih2, W_hh2, b_ih2, b_hh2);
    logits_k<<<dim3(32, 256), 256>>>(b_out, out);
}

// round 10
// speedup vs baseline: 1.5779x; 1.3915x over previous
#include <cuda_runtime.h>
#include <cstdint>
#include <cstddef>
#include <math.h>

#define NBLK 128
#define NTHR 512

// ------------------------- device scratch (static, no allocs) -------------------------
__device__ float    g_EW[4096u * 1024u];        // [row][c]: E@W_ih1[:, :256]^T + b_ih1 + b_hh1
__device__ float    g_Gpre[256u * 1024u * 64u]; // [t][c][b]: embedding gate bias per step
__device__ float    g_AllT[256u * 256u * 64u];  // [t][c][b], c<128 h2, c>=128 ctx
__device__ float    g_ET[256u * 4096u];         // E transposed: [c][v]
// state, k-major packed: idx(k,b) = (k>>2)*256 + b*4 + (k&3)
__device__ float    g_S1v[2][96 * 256];         // lstm1 input: k<128 ctx, k in [128,384) h1
__device__ float    g_S2v[2][96 * 256];         // lstm2 input: k<256 h1, k in [256,384) h2
__device__ float    g_c1[256 * 64];
__device__ float    g_c2[128 * 64];
__device__ unsigned g_slots[NBLK];

__device__ __forceinline__ float sigm(float x) { return 1.0f / (1.0f + __expf(-x)); }
__device__ __forceinline__ float ftanh(float x) {
    float cx = fminf(fmaxf(x, -15.f), 15.f);
    float e = __expf(2.f * cx);
    return (e - 1.f) / (e + 1.f);
}

// packed f32x2 helpers (sm_103a)
__device__ __forceinline__ unsigned long long pack2(float x) {
    unsigned long long r;
    asm("mov.b64 %0, {%1, %1};" : "=l"(r) : "f"(x));
    return r;
}
__device__ __forceinline__ void fma2(unsigned long long& d, unsigned long long a, unsigned long long b) {
    asm("fma.rn.f32x2 %0, %1, %2, %0;" : "+l"(d) : "l"(a), "l"(b));
}
__device__ __forceinline__ float2 unpack2(unsigned long long v) {
    float2 f;
    asm("mov.b64 {%0, %1}, %2;" : "=f"(f.x), "=f"(f.y) : "l"(v));
    return f;
}

// Atomic-free grid barrier: block i release-stores epoch to slot i; all blocks
// poll the slot vector until min >= epoch.
__device__ __forceinline__ void gbar(unsigned epoch) {
    __syncthreads();
    if (threadIdx.x == 0) {
        __threadfence();
        asm volatile("st.release.gpu.u32 [%0], %1;"
                     :: "l"(&g_slots[blockIdx.x]), "r"(epoch) : "memory");
    }
    bool ok;
    do {
        unsigned v = epoch;
        if (threadIdx.x < NBLK)
            asm volatile("ld.acquire.gpu.u32 %0, [%1];"
                         : "=r"(v) : "l"(&g_slots[threadIdx.x]) : "memory");
        ok = (v >= epoch);
    } while (!__syncthreads_and((int)ok));
}

// ------------------------- kernel 0: zero state -------------------------
__global__ void prep_k() {
    int i0 = blockIdx.x * blockDim.x + threadIdx.x;
    int st = gridDim.x * blockDim.x;
    for (int i = i0; i < 96 * 256; i += st) {
        g_S1v[0][i] = 0.f; g_S1v[1][i] = 0.f;
        g_S2v[0][i] = 0.f; g_S2v[1][i] = 0.f;
    }
    for (int i = i0; i < 256 * 64; i += st) g_c1[i] = 0.f;
    for (int i = i0; i < 128 * 64; i += st) g_c2[i] = 0.f;
    if (i0 < NBLK) g_slots[i0] = 0u;
}

// ------------------------- kernel 1: EW[v][c] = E[v,:] . W_ih1[c, :256] + bias -------------------------
__global__ void __launch_bounds__(256) ew_k(const float* __restrict__ E,
                                            const float* __restrict__ W_ih1,
                                            const float* __restrict__ b_ih1,
                                            const float* __restrict__ b_hh1) {
    __shared__ __align__(16) float sA[16][68];
    __shared__ __align__(16) float sB[16][68];
    const int c0 = blockIdx.x * 64, v0 = blockIdx.y * 64;
    const int tid = threadIdx.x;
    const int lw = tid >> 2, kq = tid & 3;
    const int cx = tid & 15, vxx = tid >> 4;
    float4 acc[4];
    acc[0] = acc[1] = acc[2] = acc[3] = make_float4(0, 0, 0, 0);
    for (int k0 = 0; k0 < 256; k0 += 16) {
        float4 av = *(const float4*)(E + (size_t)(v0 + lw) * 256 + k0 + kq * 4);
        float4 bv = *(const float4*)(W_ih1 + (size_t)(c0 + lw) * 384 + k0 + kq * 4);
        __syncthreads();
        sA[kq * 4 + 0][lw] = av.x; sA[kq * 4 + 1][lw] = av.y;
        sA[kq * 4 + 2][lw] = av.z; sA[kq * 4 + 3][lw] = av.w;
        sB[kq * 4 + 0][lw] = bv.x; sB[kq * 4 + 1][lw] = bv.y;
        sB[kq * 4 + 2][lw] = bv.z; sB[kq * 4 + 3][lw] = bv.w;
        __syncthreads();
#pragma unroll
        for (int k = 0; k < 16; k++) {
            float4 cv = *(const float4*)&sB[k][cx * 4];
            float4 vv = *(const float4*)&sA[k][vxx * 4];
            float vs[4] = {vv.x, vv.y, vv.z, vv.w};
#pragma unroll
            for (int vi = 0; vi < 4; vi++) {
                acc[vi].x = fmaf(vs[vi], cv.x, acc[vi].x);
                acc[vi].y = fmaf(vs[vi], cv.y, acc[vi].y);
                acc[vi].z = fmaf(vs[vi], cv.z, acc[vi].z);
                acc[vi].w = fmaf(vs[vi], cv.w, acc[vi].w);
            }
        }
    }
    float4 bi = *(const float4*)(b_ih1 + c0 + cx * 4);
    float4 bh = *(const float4*)(b_hh1 + c0 + cx * 4);
    float4 bias = make_float4(bi.x + bh.x, bi.y + bh.y, bi.z + bh.z, bi.w + bh.w);
#pragma unroll
    for (int vi = 0; vi < 4; vi++) {
        float4 r = make_float4(acc[vi].x + bias.x, acc[vi].y + bias.y,
                               acc[vi].z + bias.z, acc[vi].w + bias.w);
        *(float4*)(g_EW + (size_t)(v0 + vxx * 4 + vi) * 1024 + c0 + cx * 4) = r;
    }
}

// ------------------------- kernel 1b: Gpre[t][c][b] = EW[text[b][t]][c] -------------------------
__global__ void __launch_bounds__(512) gpre_k(const int* __restrict__ text) {
    const int t = blockIdx.x;
    const int tid = threadIdx.x;
    const int b = tid & 63, cs = tid >> 6;
    const int row = text[b * 256 + t] & 4095;
    const float* src = g_EW + (size_t)row * 1024;
    float* dst = g_Gpre + (size_t)t * 65536;
    for (int c = cs; c < 1024; c += 8)
        dst[c * 64 + b] = src[c];
}

// ------------------------- kernel 1c: ET[c][v] = E[v][c] -------------------------
__global__ void __launch_bounds__(256) et_k(const float* __restrict__ E) {
    __shared__ float sT[32][33];
    const int v0 = blockIdx.x * 32, c0 = blockIdx.y * 32;
    const int tx = threadIdx.x & 31, ty = threadIdx.x >> 5;
#pragma unroll
    for (int i = 0; i < 4; i++)
        sT[ty + i * 8][tx] = E[(size_t)(v0 + ty + i * 8) * 256 + c0 + tx];
    __syncthreads();
#pragma unroll
    for (int i = 0; i < 4; i++)
        g_ET[(size_t)(c0 + ty + i * 8) * 4096 + v0 + tx] = sT[tx][ty + i * 8];
}

// ------------------------- kernel 2: persistent recurrence -------------------------
__global__ void __launch_bounds__(NTHR, 1) recur_k(
    const float* __restrict__ key, const float* __restrict__ values,
    const float* __restrict__ W_ih1, const float* __restrict__ W_hh1,
    const float* __restrict__ W_ih2, const float* __restrict__ W_hh2,
    const float* __restrict__ b_ih2, const float* __restrict__ b_hh2) {
    __shared__ __align__(16) float sW1v[384 * 8];   // [k][a], a = gate*2 + jl
    __shared__ __align__(16) float sW2v[384 * 4];   // [k][q]
    __shared__ __align__(16) float sP[4096];        // partials / attention scratch
    __shared__ float sG[8 * 64];
    __shared__ float sB2[4];

    float* sEn  = sP;          // [512]
    float* sVal = sP + 512;    // [16*128]
    float* sH2f = sP + 2560;   // [128]
    float* sRed = sP + 2688;   // [32]

    const int tid = threadIdx.x;
    const int bid = blockIdx.x;
    const int b = tid & 63, ks = tid >> 6;   // 8 k-splits x 64 batch
    const int lane = tid & 31, wrp = tid >> 5;

    // weight staging (k-major)
    for (int i = tid; i < 384 * 8; i += NTHR) {
        int k = i >> 3, a = i & 7;
        int c = (a >> 1) * 256 + bid * 2 + (a & 1);
        sW1v[i] = (k < 128) ? W_ih1[(size_t)c * 384 + 256 + k]
                            : W_hh1[(size_t)c * 256 + (k - 128)];
    }
    for (int i = tid; i < 384 * 4; i += NTHR) {
        int k = i >> 2, q = i & 3;
        int c2 = q * 128 + bid;
        sW2v[i] = (k < 256) ? W_ih2[(size_t)c2 * 256 + k]
                            : W_hh2[(size_t)c2 * 128 + (k - 256)];
    }
    if (tid < 4) sB2[tid] = b_ih2[tid * 128 + bid] + b_hh2[tid * 128 + bid];
    __syncthreads();

    const int pa = tid >> 6, pb = tid & 63;
    const int pc = (pa >> 1) * 256 + bid * 2 + (pa & 1);

    unsigned ep = 0;
    for (int t = 0; t < 256; ++t) {
        const int rd = t & 1, wr = rd ^ 1;
        // prefetch step-constant / block-private values (hide L2 latency)
        float gp = __ldcg(&g_Gpre[(size_t)t * 65536 + pc * 64 + pb]);
        float c1v = 0.f, c2v = 0.f;
        if (tid < 128) c1v = g_c1[(bid * 2 + (tid >> 6)) * 64 + (tid & 63)];
        if (tid < 64)  c2v = g_c2[bid * 64 + tid];
        // ---------- P1: lstm1 gate partials (f32x2 packed) ----------
        {
            const float* Sv = g_S1v[rd];
            unsigned long long acc2[4] = {0ull, 0ull, 0ull, 0ull};
            int base = (ks * 12) * 256 + b * 4;
#pragma unroll
            for (int i = 0; i < 12; i++) {
                float4 s4 = __ldcg((const float4*)(Sv + base + i * 256));
                int kk = (ks * 12 + i) * 4;
#pragma unroll
                for (int r = 0; r < 4; r++) {
                    float sr = (r == 0) ? s4.x : (r == 1) ? s4.y : (r == 2) ? s4.z : s4.w;
                    unsigned long long sr2 = pack2(sr);
                    const ulonglong2* wp2 = (const ulonglong2*)(sW1v + (size_t)(kk + r) * 8);
                    ulonglong2 wA = wp2[0];
                    ulonglong2 wB = wp2[1];
                    fma2(acc2[0], sr2, wA.x);
                    fma2(acc2[1], sr2, wA.y);
                    fma2(acc2[2], sr2, wB.x);
                    fma2(acc2[3], sr2, wB.y);
                }
            }
#pragma unroll
            for (int p = 0; p < 4; p++) {
                float2 f = unpack2(acc2[p]);
                sP[ks * 512 + (2 * p) * 64 + b] = f.x;
                sP[ks * 512 + (2 * p + 1) * 64 + b] = f.y;
            }
        }
        __syncthreads();
        {   // combine + prefetched embedding-gate bias
            float s = gp;
#pragma unroll
            for (int k2 = 0; k2 < 8; k2++) s += sP[k2 * 512 + pa * 64 + pb];
            sG[pa * 64 + pb] = s;
        }
        __syncthreads();
        if (tid < 128) {
            int jl = tid >> 6, b2 = tid & 63;
            int j = bid * 2 + jl;
            float gi = sG[(0 + jl) * 64 + b2], gf = sG[(2 + jl) * 64 + b2];
            float gg = sG[(4 + jl) * 64 + b2], go = sG[(6 + jl) * 64 + b2];
            float cn = sigm(gf) * c1v + sigm(gi) * ftanh(gg);
            float hn = sigm(go) * ftanh(cn);
            g_c1[j * 64 + b2] = cn;
            int k1 = 128 + j;
            g_S1v[wr][(k1 >> 2) * 256 + b2 * 4 + (k1 & 3)] = hn;
            g_S2v[rd][(j >> 2) * 256 + b2 * 4 + (j & 3)] = hn;
        }
        gbar(++ep);
        // ---------- P2: lstm2 (f32x2 packed) ----------
        {
            const float* Sv = g_S2v[rd];
            unsigned long long acc2[2] = {0ull, 0ull};
            int base = (ks * 12) * 256 + b * 4;
#pragma unroll
            for (int i = 0; i < 12; i++) {
                float4 s4 = __ldcg((const float4*)(Sv + base + i * 256));
                int kk = (ks * 12 + i) * 4;
#pragma unroll
                for (int r = 0; r < 4; r++) {
                    float sr = (r == 0) ? s4.x : (r == 1) ? s4.y : (r == 2) ? s4.z : s4.w;
                    unsigned long long sr2 = pack2(sr);
                    const ulonglong2* wp2 = (const ulonglong2*)(sW2v + (size_t)(kk + r) * 4);
                    ulonglong2 w = wp2[0];
                    fma2(acc2[0], sr2, w.x);
                    fma2(acc2[1], sr2, w.y);
                }
            }
#pragma unroll
            for (int p = 0; p < 2; p++) {
                float2 f = unpack2(acc2[p]);
                sP[ks * 256 + (2 * p) * 64 + b] = f.x;
                sP[ks * 256 + (2 * p + 1) * 64 + b] = f.y;
            }
        }
        __syncthreads();
        if (tid < 256) {
            int q = tid >> 6, b2 = tid & 63;
            float s = sB2[q];
#pragma unroll
            for (int k2 = 0; k2 < 8; k2++) s += sP[k2 * 256 + q * 64 + b2];
            sG[q * 64 + b2] = s;
        }
        __syncthreads();
        if (tid < 64) {
            int b2 = tid;
            float gi = sG[0 * 64 + b2], gf = sG[1 * 64 + b2];
            float gg = sG[2 * 64 + b2], go = sG[3 * 64 + b2];
            float cn = sigm(gf) * c2v + sigm(gi) * ftanh(gg);
            float hn = sigm(go) * ftanh(cn);
            g_c2[bid * 64 + b2] = cn;
            int k2i = 256 + bid;
            g_S2v[wr][(k2i >> 2) * 256 + b2 * 4 + (k2i & 3)] = hn;
            g_AllT[(size_t)t * 16384 + bid * 64 + b2] = hn;
        }
        gbar(++ep);
        // ---------- P3: attention (blocks 0..63, one batch row each) ----------
        if (bid < 64) {
            const int b3 = bid;
            if (tid < 128) {
                int k = 256 + tid;
                sH2f[tid] = __ldcg(&g_S2v[wr][(k >> 2) * 256 + b3 * 4 + (k & 3)]);
            }
            __syncthreads();
            // energies: 8 lanes per row, fully coalesced
            {
                const float4* sH2v4 = (const float4*)sH2f;
                int ch = lane & 7, rsub = lane >> 3;
                float4 h0 = sH2v4[ch], h1v = sH2v4[ch + 8], h2v = sH2v4[ch + 16], h3v = sH2v4[ch + 24];
                const float4* kbase = (const float4*)(key + (size_t)b3 * 512 * 128);
#pragma unroll
                for (int j = 0; j < 8; j++) {
                    int row = wrp * 32 + j * 4 + rsub;
                    const float4* kp = kbase + (size_t)row * 32;
                    float4 k0 = __ldg(kp + ch), k1 = __ldg(kp + ch + 8);
                    float4 k2 = __ldg(kp + ch + 16), k3 = __ldg(kp + ch + 24);
                    float e = k0.x * h0.x;
                    e = fmaf(k0.y, h0.y, e); e = fmaf(k0.z, h0.z, e); e = fmaf(k0.w, h0.w, e);
                    e = fmaf(k1.x, h1v.x, e); e = fmaf(k1.y, h1v.y, e); e = fmaf(k1.z, h1v.z, e); e = fmaf(k1.w, h1v.w, e);
                    e = fmaf(k2.x, h2v.x, e); e = fmaf(k2.y, h2v.y, e); e = fmaf(k2.z, h2v.z, e); e = fmaf(k2.w, h2v.w, e);
                    e = fmaf(k3.x, h3v.x, e); e = fmaf(k3.y, h3v.y, e); e = fmaf(k3.z, h3v.z, e); e = fmaf(k3.w, h3v.w, e);
                    e += __shfl_xor_sync(0xffffffffu, e, 4);
                    e += __shfl_xor_sync(0xffffffffu, e, 2);
                    e += __shfl_xor_sync(0xffffffffu, e, 1);
                    if (ch == 0) sEn[row] = e;
                }
            }
            __syncthreads();
            // softmax over 512
            float e = sEn[tid];
            float m = e;
#pragma unroll
            for (int off = 16; off > 0; off >>= 1) m = fmaxf(m, __shfl_xor_sync(0xffffffffu, m, off));
            if (lane == 0) sRed[wrp] = m;
            __syncthreads();
            if (tid < 32) {
                float mm = (tid < 16) ? sRed[tid] : -3.402823466e38f;
#pragma unroll
                for (int off = 8; off > 0; off >>= 1) mm = fmaxf(mm, __shfl_xor_sync(0xffffffffu, mm, off));
                if (tid == 0) sRed[16] = mm;
            }
            __syncthreads();
            float mx = sRed[16];
            float ex = __expf(e - mx);
            sEn[tid] = ex;
            float ssum = ex;
#pragma unroll
            for (int off = 16; off > 0; off >>= 1) ssum += __shfl_xor_sync(0xffffffffu, ssum, off);
            if (lane == 0) sRed[wrp] = ssum;
            __syncthreads();
            if (tid < 32) {
                float tt = (tid < 16) ? sRed[tid] : 0.f;
#pragma unroll
                for (int off = 8; off > 0; off >>= 1) tt += __shfl_xor_sync(0xffffffffu, tt, off);
                if (tid == 0) sRed[17] = tt;
            }
            __syncthreads();
            // weighted values: 32 float4-cols x 16 tp-groups
            {
                int v4 = tid & 31, g = tid >> 5;
                const float* vb = values + (size_t)b3 * 65536 + v4 * 4;
                float4 a4 = make_float4(0.f, 0.f, 0.f, 0.f);
#pragma unroll 8
                for (int i = 0; i < 32; i++) {
                    int tp = g * 32 + i;
                    float wgt = sEn[tp];
                    float4 vv = __ldg((const float4*)(vb + (size_t)tp * 128));
                    a4.x = fmaf(wgt, vv.x, a4.x); a4.y = fmaf(wgt, vv.y, a4.y);
                    a4.z = fmaf(wgt, vv.z, a4.z); a4.w = fmaf(wgt, vv.w, a4.w);
                }
                ((float4*)(sVal + g * 128))[v4] = a4;
            }
            __syncthreads();
            if (tid < 128) {
                float s = 0.f;
#pragma unroll
                for (int g2 = 0; g2 < 16; g2++) s += sVal[g2 * 128 + tid];
                float cv = s / sRed[17];
                g_S1v[wr][(tid >> 2) * 256 + b3 * 4 + (tid & 3)] = cv;
                g_AllT[(size_t)t * 16384 + (128 + tid) * 64 + b3] = cv;
            }
        }
        gbar(++ep);
    }
}

// ------------------------- kernel 3: logits = AllT^T @ ET + b_out -------------------------
__global__ void __launch_bounds__(256) logits_k(const float* __restrict__ b_out,
                                                float* __restrict__ out) {
    __shared__ __align__(16) float sX[16 * 64];
    __shared__ __align__(16) float sE[16 * 128];
    const int v0 = blockIdx.x * 128;
    const int t = blockIdx.y;
    const int tid = threadIdx.x;
    const int vx = tid & 31, bx = tid >> 5;
    float4 acc[8];
#pragma unroll
    for (int i = 0; i < 8; i++) acc[i] = make_float4(0, 0, 0, 0);

    const int kl = tid >> 4, bq = tid & 15;
    const int ke = tid >> 5, ve = tid & 31;

    for (int c0 = 0; c0 < 256; c0 += 16) {
        float4 xv = *(const float4*)(g_AllT + (size_t)t * 16384 + (size_t)(c0 + kl) * 64 + bq * 4);
        float4 e0 = *(const float4*)(g_ET + (size_t)(c0 + ke) * 4096 + v0 + ve * 4);
        float4 e1 = *(const float4*)(g_ET + (size_t)(c0 + ke + 8) * 4096 + v0 + ve * 4);
        __syncthreads();
        *(float4*)&sX[kl * 64 + bq * 4] = xv;
        *(float4*)&sE[ke * 128 + ve * 4] = e0;
        *(float4*)&sE[(ke + 8) * 128 + ve * 4] = e1;
        __syncthreads();
#pragma unroll
        for (int k = 0; k < 16; k++) {
            float4 ev = *(const float4*)&sE[k * 128 + vx * 4];
            float4 x0 = *(const float4*)&sX[k * 64 + bx * 8];
            float4 x1 = *(const float4*)&sX[k * 64 + bx * 8 + 4];
            float xs[8] = {x0.x, x0.y, x0.z, x0.w, x1.x, x1.y, x1.z, x1.w};
#pragma unroll
            for (int j = 0; j < 8; j++) {
                acc[j].x = fmaf(xs[j], ev.x, acc[j].x);
                acc[j].y = fmaf(xs[j], ev.y, acc[j].y);
                acc[j].z = fmaf(xs[j], ev.z, acc[j].z);
                acc[j].w = fmaf(xs[j], ev.w, acc[j].w);
            }
        }
    }
    float4 bo = *(const float4*)(b_out + v0 + vx * 4);
#pragma unroll
    for (int j = 0; j < 8; j++) {
        int bb = bx * 8 + j;
        float4 r = make_float4(acc[j].x + bo.x, acc[j].y + bo.y,
                               acc[j].z + bo.z, acc[j].w + bo.w);
        *(float4*)(out + ((size_t)bb * 256 + t) * 4096 + v0 + vx * 4) = r;
    }
}

// ------------------------- launch -------------------------
extern "C" void kernel_launch(void* const* d_in, const int* in_sizes, int n_in,
                              void* d_out, int out_size) {
    (void)in_sizes; (void)n_in; (void)out_size;
    const float* key    = (const float*)d_in[0];
    const float* values = (const float*)d_in[1];
    const int*   text   = (const int*)d_in[3];
    const float* E      = (const float*)d_in[4];
    const float* W_ih1  = (const float*)d_in[5];
    const float* W_hh1  = (const float*)d_in[6];
    const float* b_ih1  = (const float*)d_in[7];
    const float* b_hh1  = (const float*)d_in[8];
    const float* W_ih2  = (const float*)d_in[9];
    const float* W_hh2  = (const float*)d_in[10];
    const float* b_ih2  = (const float*)d_in[11];
    const float* b_hh2  = (const float*)d_in[12];
    const float* b_out  = (const float*)d_in[13];
    float*       out    = (float*)d_out;

    prep_k<<<128, 256>>>();
    ew_k<<<dim3(16, 64), 256>>>(E, W_ih1, b_ih1, b_hh1);
    gpre_k<<<256, 512>>>(text);
    et_k<<<dim3(128, 8), 256>>>(E);
    recur_k<<<NBLK, NTHR>>>(key, values, W_ih1, W_hh1, W_ih2, W_hh2, b_ih2, b_hh2);
    logits_k<<<dim3(32, 256), 256>>>(b_out, out);
}